// round 5
// baseline (speedup 1.0000x reference)
#include <cuda_runtime.h>
#include <cuda_fp16.h>
#include <math.h>
#include <stdint.h>

#define Bc     8
#define Nc     1000
#define Dc     64
#define ADc    32
#define NEc    4000      // E * N
#define ACOLS  8000      // 2 * E * N
#define KCH    32        // K per chunk
#define NCHUNK 125       // 4000 / 32
#define ASTR   40        // padded smem stride in halves (80B: conflict-free ldmatrix)

// Scratch (static device globals; no allocation)
__device__ __half g_sT[2][Bc][Dc][NEc];   // S^T (fp16), B operand: n-major rows of k
__device__ float  g_a[2][Bc][Nc][Dc];     // a_in / a_out
__device__ float  g_state[2][Bc][Nc][Dc]; // s1 / s2

// ---------------------------------------------------------------------------
// helpers
// ---------------------------------------------------------------------------
__device__ __forceinline__ void cp_async16(uint32_t dst, const void* src) {
    asm volatile("cp.async.cg.shared.global [%0], [%1], 16;\n" :: "r"(dst), "l"(src));
}
__device__ __forceinline__ void cp_commit() {
    asm volatile("cp.async.commit_group;\n");
}
__device__ __forceinline__ void ldm4(uint32_t* r, uint32_t addr) {
    asm volatile("ldmatrix.sync.aligned.m8n8.x4.shared.b16 {%0,%1,%2,%3}, [%4];"
                 : "=r"(r[0]), "=r"(r[1]), "=r"(r[2]), "=r"(r[3]) : "r"(addr));
}
__device__ __forceinline__ void mma_f16(float* c, const uint32_t* a,
                                        uint32_t b0, uint32_t b1) {
    asm volatile("mma.sync.aligned.m16n8k16.row.col.f32.f16.f16.f32 "
                 "{%0,%1,%2,%3},{%4,%5,%6,%7},{%8,%9},{%0,%1,%2,%3};"
                 : "+f"(c[0]), "+f"(c[1]), "+f"(c[2]), "+f"(c[3])
                 : "r"(a[0]), "r"(a[1]), "r"(a[2]), "r"(a[3]), "r"(b0), "r"(b1));
}
__device__ __forceinline__ uint32_t packh2(float a, float b) {
    __half2 h = __floats2half2_rn(a, b);
    return *(uint32_t*)&h;
}

// ---------------------------------------------------------------------------
// s projection (tiled GEMM) -> writes S^T in fp16:
//   g_sT[half][b][f][e*1000+n] = sum_d state[b,n,d] * W{half}[e,f,d]
// grid (125, 8), block 256.
// ---------------------------------------------------------------------------
__global__ void __launch_bounds__(256) k_compute_s2(
    const float* __restrict__ Xext, int use_ext,
    const float* __restrict__ W_in, const float* __restrict__ W_out) {
    const float* X = use_ext ? Xext : &g_state[0][0][0][0];
    int rb = blockIdx.x, cb = blockIdx.y;
    __shared__ float smbuf[2 * 64 * 64];
    float (*x_sm)[64] = (float(*)[64])smbuf;
    float (*wT)[64]   = (float(*)[64])(smbuf + 64 * 64);
    int t = threadIdx.x;

#pragma unroll
    for (int i = 0; i < 4; i++) {
        int idx = i * 256 + t;
        int r = idx >> 4, c4 = idx & 15;
        int gr = rb * 64 + r;
        *(float4*)&x_sm[r][c4 * 4] = *(const float4*)&X[(size_t)gr * 64 + c4 * 4];
    }
    const float* Wsrc = (cb < 4) ? (W_in + (size_t)cb * 64 * 64)
                                 : (W_out + (size_t)(cb - 4) * 64 * 64);
#pragma unroll
    for (int i = 0; i < 4; i++) {
        int idx = i * 256 + t;
        int cl = idx >> 4, k4 = idx & 15;
        float4 v = *(const float4*)&Wsrc[cl * 64 + k4 * 4];
        wT[k4 * 4 + 0][cl] = v.x;
        wT[k4 * 4 + 1][cl] = v.y;
        wT[k4 * 4 + 2][cl] = v.z;
        wT[k4 * 4 + 3][cl] = v.w;
    }
    __syncthreads();

    int ty = t >> 5, tx = t & 31;
    float acc[8][2];
#pragma unroll
    for (int i = 0; i < 8; i++) { acc[i][0] = 0.f; acc[i][1] = 0.f; }

#pragma unroll
    for (int k4 = 0; k4 < 16; k4++) {
        float4 xv[8];
#pragma unroll
        for (int i = 0; i < 8; i++) xv[i] = *(float4*)&x_sm[ty * 8 + i][k4 * 4];
#pragma unroll
        for (int q = 0; q < 4; q++) {
            float2 wv = *(float2*)&wT[k4 * 4 + q][tx * 2];
#pragma unroll
            for (int i = 0; i < 8; i++) {
                float xs = (q == 0) ? xv[i].x : (q == 1) ? xv[i].y
                         : (q == 2) ? xv[i].z : xv[i].w;
                acc[i][0] += xs * wv.x;
                acc[i][1] += xs * wv.y;
            }
        }
    }
    __syncthreads();   // x_sm / wT dead; reuse smbuf for transpose

    float (*t_sm)[65] = (float(*)[65])smbuf;
#pragma unroll
    for (int i = 0; i < 8; i++) {
        t_sm[ty * 8 + i][tx * 2 + 0] = acc[i][0];
        t_sm[ty * 8 + i][tx * 2 + 1] = acc[i][1];
    }
    __syncthreads();

    // transposed, coalesced-ish fp16 write: lanes run along n
    int r = t & 63, q = t >> 6;
    int gr = rb * 64 + r;
    int b = gr / 1000, n = gr % 1000;
    int half = cb >> 2, e = cb & 3;
    __half* dst = &g_sT[half][b][0][e * 1000 + n];
#pragma unroll
    for (int j = 0; j < 16; j++) {
        int f = q * 16 + j;
        dst[(size_t)f * NEc] = __float2half_rn(t_sm[r][f]);
    }
}

// ---------------------------------------------------------------------------
// Big adjacency GEMM, fp16 mma.m16n8k16 + ldmatrix:
//   C[row][f] = sum_k A[row][k] * sT[f][k]
// grid (8, 2, 8), 256 threads (8 warps: 4m x 2n, warp tile 32x32).
// A: LDG fp32 (coalesced) -> cvt fp16 -> STS, double-buffered + 1-iter reg prefetch.
// B: cp.async fp16 from g_sT, triple-buffered.
// ---------------------------------------------------------------------------
__global__ void __launch_bounds__(256) k_biggemm_f16(const float* __restrict__ A) {
    __shared__ __half A_smh[2][128 * ASTR];   // 20480 B
    __shared__ __half B_smh[3][64 * ASTR];    // 15360 B

    int rb = blockIdx.x, half = blockIdx.y, b = blockIdx.z;
    int row0 = rb * 128;
    const float*  Ab = A + (size_t)b * Nc * ACOLS + (size_t)half * NEc;
    const __half* Sb = &g_sT[half][b][0][0];

    int t = threadIdx.x, lane = t & 31, warp = t >> 5;
    int wm = warp & 3, wn = warp >> 2;

    // ---- A load mapping: thread t, j=0..3: flat = j*256+t; row=flat>>3 c=flat&7
    const float* aptr[4]; int asts[4];
#pragma unroll
    for (int j = 0; j < 4; j++) {
        int flat = j * 256 + t;
        int row = flat >> 3, c = flat & 7;
        int gr = row0 + row; if (gr > Nc - 1) gr = Nc - 1;
        aptr[j] = Ab + (size_t)gr * ACOLS + c * 4;
        asts[j] = row * ASTR + c * 4;          // half index in buffer
    }
    // ---- B cp.async mapping: thread t: row = t>>2 (n), seg = t&3 (8 halves)
    int brow = t >> 2, bseg = t & 3;
    const __half* bptr = Sb + (size_t)brow * NEc + bseg * 8;
    uint32_t bdst[3];
#pragma unroll
    for (int s = 0; s < 3; s++)
        bdst[s] = (uint32_t)__cvta_generic_to_shared(&B_smh[s][brow * ASTR + bseg * 8]);

    // ---- ldmatrix addresses (byte offsets within a buffer) ----
    uint32_t a_base[2], b_base[3];
#pragma unroll
    for (int s = 0; s < 2; s++) a_base[s] = (uint32_t)__cvta_generic_to_shared(&A_smh[s][0]);
#pragma unroll
    for (int s = 0; s < 3; s++) b_base[s] = (uint32_t)__cvta_generic_to_shared(&B_smh[s][0]);

    uint32_t a_off[2][2];   // [mt][kk]
#pragma unroll
    for (int mt = 0; mt < 2; mt++)
#pragma unroll
        for (int kk = 0; kk < 2; kk++) {
            int row = wm * 32 + mt * 16 + ((lane >> 3) & 1) * 8 + (lane & 7);
            int col = kk * 16 + (lane >> 4) * 8;
            a_off[mt][kk] = (uint32_t)(row * ASTR + col) * 2u;
        }
    uint32_t b_off[2][2];   // [g][kk]
#pragma unroll
    for (int g = 0; g < 2; g++)
#pragma unroll
        for (int kk = 0; kk < 2; kk++) {
            int row = wn * 32 + g * 16 + ((lane >> 3) & 1) * 8 + (lane & 7);
            int col = kk * 16 + (lane >> 4) * 8;
            b_off[g][kk] = (uint32_t)(row * ASTR + col) * 2u;
        }

    float acc[2][4][4];
#pragma unroll
    for (int mt = 0; mt < 2; mt++)
#pragma unroll
        for (int nt = 0; nt < 4; nt++)
#pragma unroll
            for (int c = 0; c < 4; c++) acc[mt][nt][c] = 0.f;

    // ---- prologue ----
    float4 ra[4];
#pragma unroll
    for (int j = 0; j < 4; j++) ra[j] = *(const float4*)(aptr[j]);        // A0
#pragma unroll
    for (int j = 0; j < 4; j++) {
        *(uint2*)&A_smh[0][asts[j]] = make_uint2(packh2(ra[j].x, ra[j].y),
                                                 packh2(ra[j].z, ra[j].w));
    }
#pragma unroll
    for (int j = 0; j < 4; j++) ra[j] = *(const float4*)(aptr[j] + KCH);  // A1

    cp_async16(bdst[0], bptr);            cp_commit();   // B0
    cp_async16(bdst[1], bptr + KCH);      cp_commit();   // B1

    for (int i = 0; i < NCHUNK; i++) {
        asm volatile("cp.async.wait_group 1;\n");
        __syncthreads();

        if (i < NCHUNK - 1) {
            int nb = (i + 1) & 1;
#pragma unroll
            for (int j = 0; j < 4; j++) {
                *(uint2*)&A_smh[nb][asts[j]] = make_uint2(packh2(ra[j].x, ra[j].y),
                                                          packh2(ra[j].z, ra[j].w));
            }
        }
        if (i < NCHUNK - 2) {
            int kt = (i + 2) * KCH;
#pragma unroll
            for (int j = 0; j < 4; j++) ra[j] = *(const float4*)(aptr[j] + kt);
            cp_async16(bdst[(i + 2) % 3], bptr + kt);
        }
        cp_commit();

        // ---- fragments + MMAs on chunk i ----
        uint32_t ab = a_base[i & 1], bb = b_base[i % 3];
        uint32_t aF[2][2][4];    // [kk][mt][4]
        uint32_t bF[2][2][4];    // [kk][g][4]
#pragma unroll
        for (int kk = 0; kk < 2; kk++)
#pragma unroll
            for (int mt = 0; mt < 2; mt++) ldm4(aF[kk][mt], ab + a_off[mt][kk]);
#pragma unroll
        for (int kk = 0; kk < 2; kk++)
#pragma unroll
            for (int g = 0; g < 2; g++) ldm4(bF[kk][g], bb + b_off[g][kk]);

#pragma unroll
        for (int kk = 0; kk < 2; kk++)
#pragma unroll
            for (int mt = 0; mt < 2; mt++)
#pragma unroll
                for (int nt = 0; nt < 4; nt++) {
                    int g = nt >> 1, sel = nt & 1;
                    mma_f16(acc[mt][nt], aF[kk][mt],
                            bF[kk][g][sel], bF[kk][g][2 + sel]);
                }
        __syncthreads();
    }

    // ---- epilogue: direct global stores ----
    float (*C)[Dc] = g_a[half][b];
#pragma unroll
    for (int mt = 0; mt < 2; mt++) {
        int r_a = row0 + wm * 32 + mt * 16 + (lane >> 2);
        int r_b = r_a + 8;
#pragma unroll
        for (int nt = 0; nt < 4; nt++) {
            int col = wn * 32 + nt * 8 + (lane & 3) * 2;
            if (r_a < Nc) *(float2*)&C[r_a][col] = make_float2(acc[mt][nt][0], acc[mt][nt][1]);
            if (r_b < Nc) *(float2*)&C[r_b][col] = make_float2(acc[mt][nt][2], acc[mt][nt][3]);
        }
    }
}

// ---------------------------------------------------------------------------
// GRU update. a = [a_in | a_out | state] (192)
// ---------------------------------------------------------------------------
__global__ void k_gru(const float* __restrict__ ext_state, int use_ext, int out_idx,
                      const float* __restrict__ W_r,
                      const float* __restrict__ W_z,
                      const float* __restrict__ W_h) {
    __shared__ float a_sm[16][192];
    __shared__ float rs_sm[16][64];
    int t = threadIdx.x;
    int base = blockIdx.x * 16;

#pragma unroll
    for (int c = 0; c < 3; c++) {
        int idx = c * 256 + t;
        int lr  = idx / 48;
        int j4  = idx % 48;
        int bn  = base + lr;
        int b = bn / Nc, n = bn % Nc;
        float4 v;
        if (j4 < 16)      v = *(const float4*)&g_a[0][b][n][j4 * 4];
        else if (j4 < 32) v = *(const float4*)&g_a[1][b][n][(j4 - 16) * 4];
        else {
            const float* sp = use_ext ? (ext_state + (size_t)bn * Dc)
                                      : &g_state[0][b][n][0];
            v = *(const float4*)&sp[(j4 - 32) * 4];
        }
        *(float4*)&a_sm[lr][j4 * 4] = v;
    }
    __syncthreads();

    int f = t & 63, q = t >> 6;
    const float4* Wr4 = (const float4*)(W_r + (size_t)f * 192);
    const float4* Wz4 = (const float4*)(W_z + (size_t)f * 192);
    const float4* Wh4 = (const float4*)(W_h + (size_t)f * 192);

    float pr[4] = {0, 0, 0, 0}, pz[4] = {0, 0, 0, 0}, h1[4] = {0, 0, 0, 0};

#pragma unroll 4
    for (int j4 = 0; j4 < 32; j4++) {
        float4 wr = Wr4[j4], wz = Wz4[j4], wh = Wh4[j4];
#pragma unroll
        for (int g = 0; g < 4; g++) {
            float4 av = *(float4*)&a_sm[q * 4 + g][j4 * 4];
            pr[g] += wr.x * av.x + wr.y * av.y + wr.z * av.z + wr.w * av.w;
            pz[g] += wz.x * av.x + wz.y * av.y + wz.z * av.z + wz.w * av.w;
            h1[g] += wh.x * av.x + wh.y * av.y + wh.z * av.z + wh.w * av.w;
        }
    }
#pragma unroll 4
    for (int j4 = 32; j4 < 48; j4++) {
        float4 wr = Wr4[j4], wz = Wz4[j4];
#pragma unroll
        for (int g = 0; g < 4; g++) {
            float4 av = *(float4*)&a_sm[q * 4 + g][j4 * 4];
            pr[g] += wr.x * av.x + wr.y * av.y + wr.z * av.z + wr.w * av.w;
            pz[g] += wz.x * av.x + wz.y * av.y + wz.z * av.z + wz.w * av.w;
        }
    }

#pragma unroll
    for (int g = 0; g < 4; g++) {
        float r = 1.f / (1.f + expf(-pr[g]));
        rs_sm[q * 4 + g][f] = r * a_sm[q * 4 + g][128 + f];
    }
    __syncthreads();

#pragma unroll 4
    for (int j4 = 0; j4 < 16; j4++) {
        float4 wh = Wh4[32 + j4];
#pragma unroll
        for (int g = 0; g < 4; g++) {
            float4 rv = *(float4*)&rs_sm[q * 4 + g][j4 * 4];
            h1[g] += wh.x * rv.x + wh.y * rv.y + wh.z * rv.z + wh.w * rv.w;
        }
    }

#pragma unroll
    for (int g = 0; g < 4; g++) {
        int lr = q * 4 + g;
        int bn = base + lr;
        int b = bn / Nc, n = bn % Nc;
        float st = a_sm[lr][128 + f];
        float z  = 1.f / (1.f + expf(-pz[g]));
        float h  = tanhf(h1[g]);
        g_state[out_idx][b][n][f] = (1.f - z) * st + z * h;
    }
}

// ---------------------------------------------------------------------------
// out[b,n] = sum_f tanh( sum_{j<96} [s2|annot][j] * Wo1[f,j] ) * Wo2[f]
// ---------------------------------------------------------------------------
__global__ void k_final(const float* __restrict__ annotation,
                        const float* __restrict__ Wo1,
                        const float* __restrict__ Wo2,
                        float* __restrict__ out) {
    __shared__ float join[4][96];
    __shared__ float terms[4][64];
    int t = threadIdx.x;
    int base = blockIdx.x * 4;

    for (int idx = t; idx < 4 * 96; idx += 256) {
        int lr = idx / 96, j = idx % 96;
        int bn = base + lr;
        int b = bn / Nc, n = bn % Nc;
        join[lr][j] = (j < Dc) ? g_state[1][b][n][j]
                               : annotation[(size_t)bn * ADc + (j - Dc)];
    }
    __syncthreads();

    int f = t & 63, q = t >> 6;
    const float4* w = (const float4*)(Wo1 + (size_t)f * 96);
    float acc = 0.f;
#pragma unroll
    for (int j4 = 0; j4 < 24; j4++) {
        float4 wv = w[j4];
        float4 jv = *(float4*)&join[q][j4 * 4];
        acc += wv.x * jv.x + wv.y * jv.y + wv.z * jv.z + wv.w * jv.w;
    }
    terms[q][f] = tanhf(acc) * Wo2[f];
    __syncthreads();

    if (f == 0) {
        float s = 0.f;
#pragma unroll
        for (int i = 0; i < Dc; i++) s += terms[q][i];
        out[base + q] = s;
    }
}

// ---------------------------------------------------------------------------
extern "C" void kernel_launch(void* const* d_in, const int* in_sizes, int n_in,
                              void* d_out, int out_size) {
    const float* prop_state = (const float*)d_in[0];
    const float* annotation = (const float*)d_in[1];
    const float* A          = (const float*)d_in[2];
    const float* W_in       = (const float*)d_in[3];
    const float* W_out      = (const float*)d_in[4];
    const float* W_r        = (const float*)d_in[5];
    const float* W_z        = (const float*)d_in[6];
    const float* W_h        = (const float*)d_in[7];
    const float* Wo1        = (const float*)d_in[8];
    const float* Wo2        = (const float*)d_in[9];
    float* out = (float*)d_out;

    dim3 s_grid(125, 8);
    dim3 gemm_grid(8, 2, Bc);

    // ---- propagate step 1 (state = prop_state) ----
    k_compute_s2<<<s_grid, 256>>>(prop_state, 1, W_in, W_out);
    k_biggemm_f16<<<gemm_grid, 256>>>(A);
    k_gru<<<Bc * Nc / 16, 256>>>(prop_state, 1, 0, W_r, W_z, W_h);

    // ---- propagate step 2 (state = g_state[0]) ----
    k_compute_s2<<<s_grid, 256>>>(nullptr, 0, W_in, W_out);
    k_biggemm_f16<<<gemm_grid, 256>>>(A);
    k_gru<<<Bc * Nc / 16, 256>>>(nullptr, 0, 1, W_r, W_z, W_h);

    // ---- output head ----
    k_final<<<Bc * Nc / 4, 256>>>(annotation, Wo1, Wo2, out);
}

// round 6
// speedup vs baseline: 1.8561x; 1.8561x over previous
#include <cuda_runtime.h>
#include <cuda_fp16.h>
#include <math.h>
#include <stdint.h>

#define Bc     8
#define Nc     1000
#define Dc     64
#define ADc    32
#define NEc    4000      // E * N
#define ACOLS  8000      // 2 * E * N
#define KCH    32        // K per chunk
#define NCHUNK 125       // 4000 / 32
#define ASTR   40        // A smem stride (halves)
#define BSTR   72        // B smem stride (halves)

// Scratch (static device globals; no allocation)
__device__ __half g_Ah[(size_t)Bc * Nc * ACOLS];   // fp16 copy of A (128 MB)
__device__ __half g_sh[2][Bc][NEc][Dc];            // S (fp16), [m][f] k-major rows
__device__ float  g_a[2][Bc][Nc][Dc];              // a_in / a_out
__device__ float  g_state[2][Bc][Nc][Dc];          // s1 / s2

// ---------------------------------------------------------------------------
// helpers
// ---------------------------------------------------------------------------
__device__ __forceinline__ void cp_async16(uint32_t dst, const void* src) {
    asm volatile("cp.async.cg.shared.global [%0], [%1], 16;\n" :: "r"(dst), "l"(src));
}
__device__ __forceinline__ void cp_commit() {
    asm volatile("cp.async.commit_group;\n");
}
__device__ __forceinline__ void ldm4(uint32_t* r, uint32_t addr) {
    asm volatile("ldmatrix.sync.aligned.m8n8.x4.shared.b16 {%0,%1,%2,%3}, [%4];"
                 : "=r"(r[0]), "=r"(r[1]), "=r"(r[2]), "=r"(r[3]) : "r"(addr));
}
__device__ __forceinline__ void ldm4t(uint32_t* r, uint32_t addr) {
    asm volatile("ldmatrix.sync.aligned.m8n8.x4.trans.shared.b16 {%0,%1,%2,%3}, [%4];"
                 : "=r"(r[0]), "=r"(r[1]), "=r"(r[2]), "=r"(r[3]) : "r"(addr));
}
__device__ __forceinline__ void mma_f16(float* c, const uint32_t* a,
                                        uint32_t b0, uint32_t b1) {
    asm volatile("mma.sync.aligned.m16n8k16.row.col.f32.f16.f16.f32 "
                 "{%0,%1,%2,%3},{%4,%5,%6,%7},{%8,%9},{%0,%1,%2,%3};"
                 : "+f"(c[0]), "+f"(c[1]), "+f"(c[2]), "+f"(c[3])
                 : "r"(a[0]), "r"(a[1]), "r"(a[2]), "r"(a[3]), "r"(b0), "r"(b1));
}

// ---------------------------------------------------------------------------
// A fp32 -> fp16 (one pass, reused by both propagate steps)
// ---------------------------------------------------------------------------
__global__ void __launch_bounds__(256) k_convA(const float* __restrict__ A) {
    size_t idx = (size_t)blockIdx.x * 256 + threadIdx.x;   // one float4 each
    float4 v = ((const float4*)A)[idx];
    __half2 h0 = __floats2half2_rn(v.x, v.y);
    __half2 h1 = __floats2half2_rn(v.z, v.w);
    uint2 o = make_uint2(*(uint32_t*)&h0, *(uint32_t*)&h1);
    ((uint2*)g_Ah)[idx] = o;
}

// ---------------------------------------------------------------------------
// s projection (tiled GEMM) -> fp16 S, k-major rows:
//   g_sh[half][b][e*1000+n][f] = sum_d state[b,n,d] * W{half}[e,f,d]
// grid (125, 8), block 256.
// ---------------------------------------------------------------------------
__global__ void __launch_bounds__(256) k_compute_s2(
    const float* __restrict__ Xext, int use_ext,
    const float* __restrict__ W_in, const float* __restrict__ W_out) {
    const float* X = use_ext ? Xext : &g_state[0][0][0][0];
    int rb = blockIdx.x, cb = blockIdx.y;
    __shared__ float x_sm[64][64];
    __shared__ float wT[64][64];
    int t = threadIdx.x;

#pragma unroll
    for (int i = 0; i < 4; i++) {
        int idx = i * 256 + t;
        int r = idx >> 4, c4 = idx & 15;
        int gr = rb * 64 + r;
        *(float4*)&x_sm[r][c4 * 4] = *(const float4*)&X[(size_t)gr * 64 + c4 * 4];
    }
    const float* Wsrc = (cb < 4) ? (W_in + (size_t)cb * 64 * 64)
                                 : (W_out + (size_t)(cb - 4) * 64 * 64);
#pragma unroll
    for (int i = 0; i < 4; i++) {
        int idx = i * 256 + t;
        int cl = idx >> 4, k4 = idx & 15;
        float4 v = *(const float4*)&Wsrc[cl * 64 + k4 * 4];
        wT[k4 * 4 + 0][cl] = v.x;
        wT[k4 * 4 + 1][cl] = v.y;
        wT[k4 * 4 + 2][cl] = v.z;
        wT[k4 * 4 + 3][cl] = v.w;
    }
    __syncthreads();

    int ty = t >> 5, tx = t & 31;
    float acc[8][2];
#pragma unroll
    for (int i = 0; i < 8; i++) { acc[i][0] = 0.f; acc[i][1] = 0.f; }

#pragma unroll
    for (int k4 = 0; k4 < 16; k4++) {
        float4 xv[8];
#pragma unroll
        for (int i = 0; i < 8; i++) xv[i] = *(float4*)&x_sm[ty * 8 + i][k4 * 4];
#pragma unroll
        for (int q = 0; q < 4; q++) {
            float2 wv = *(float2*)&wT[k4 * 4 + q][tx * 2];
#pragma unroll
            for (int i = 0; i < 8; i++) {
                float xs = (q == 0) ? xv[i].x : (q == 1) ? xv[i].y
                         : (q == 2) ? xv[i].z : xv[i].w;
                acc[i][0] += xs * wv.x;
                acc[i][1] += xs * wv.y;
            }
        }
    }

    int cbase = cb * 64 + tx * 2;
    int half = cbase >> 8, e = (cbase >> 6) & 3, f = cbase & 63;
#pragma unroll
    for (int i = 0; i < 8; i++) {
        int gr = rb * 64 + ty * 8 + i;
        int b = gr / 1000, n = gr % 1000;
        __half2 hv = __floats2half2_rn(acc[i][0], acc[i][1]);
        *(__half2*)&g_sh[half][b][e * 1000 + n][f] = hv;
    }
}

// ---------------------------------------------------------------------------
// Big adjacency GEMM, fp16 mma + ldmatrix, full cp.async 4-stage pipeline:
//   C[row][f] = sum_k Ah[row][k] * sh[k][f]
// grid (8, 2, 8), 256 threads (8 warps: 4m x 2n, warp tile 32x32).
// ---------------------------------------------------------------------------
__global__ void __launch_bounds__(256) k_biggemm_f16(int dummy) {
    __shared__ __half Asm[4][128 * ASTR];   // 4 x 10240 B
    __shared__ __half Bsm[4][32 * BSTR];    // 4 x 4608 B

    int rb = blockIdx.x, half = blockIdx.y, b = blockIdx.z;
    int row0 = rb * 128;
    const __half* Abh = g_Ah + (size_t)b * Nc * ACOLS + (size_t)half * NEc;
    const __half* Sbh = &g_sh[half][b][0][0];

    int t = threadIdx.x, lane = t & 31, warp = t >> 5;
    int wm = warp & 3, wn = warp >> 2;

    // cp.async mappings
    const __half* asrc[2]; uint32_t adst[2];
#pragma unroll
    for (int j = 0; j < 2; j++) {
        int flat = j * 256 + t;
        int row = flat >> 2, seg = flat & 3;           // 128 rows x 4 x 16B
        int gr = row0 + row; if (gr > Nc - 1) gr = Nc - 1;
        asrc[j] = Abh + (size_t)gr * ACOLS + seg * 8;
        adst[j] = (uint32_t)(row * ASTR + seg * 8) * 2u;
    }
    int brow = t >> 3, bseg = t & 7;                   // 32 rows x 8 x 16B
    const __half* bsrc = Sbh + (size_t)brow * Dc + bseg * 8;
    uint32_t bdst = (uint32_t)(brow * BSTR + bseg * 8) * 2u;

    uint32_t a_base[4], b_base[4];
#pragma unroll
    for (int s = 0; s < 4; s++) {
        a_base[s] = (uint32_t)__cvta_generic_to_shared(&Asm[s][0]);
        b_base[s] = (uint32_t)__cvta_generic_to_shared(&Bsm[s][0]);
    }

    // ldmatrix offsets
    uint32_t a_off[2][2];   // [mt][kk]
#pragma unroll
    for (int mt = 0; mt < 2; mt++)
#pragma unroll
        for (int kk = 0; kk < 2; kk++) {
            int row = wm * 32 + mt * 16 + ((lane >> 3) & 1) * 8 + (lane & 7);
            int col = kk * 16 + (lane >> 4) * 8;
            a_off[mt][kk] = (uint32_t)(row * ASTR + col) * 2u;
        }
    uint32_t b_off[2][2];   // [g][kk]  (trans: rows k, cols n)
#pragma unroll
    for (int g = 0; g < 2; g++)
#pragma unroll
        for (int kk = 0; kk < 2; kk++) {
            int krow = kk * 16 + (lane & 15);
            int ncol = wn * 32 + g * 16 + (lane >> 4) * 8;
            b_off[g][kk] = (uint32_t)(krow * BSTR + ncol) * 2u;
        }

    float acc[2][4][4];
#pragma unroll
    for (int mt = 0; mt < 2; mt++)
#pragma unroll
        for (int nt = 0; nt < 4; nt++)
#pragma unroll
            for (int c = 0; c < 4; c++) acc[mt][nt][c] = 0.f;

    // prologue: chunks 0..2
#pragma unroll
    for (int ch = 0; ch < 3; ch++) {
        int kt = ch * KCH;
#pragma unroll
        for (int j = 0; j < 2; j++) cp_async16(a_base[ch] + adst[j], asrc[j] + kt);
        cp_async16(b_base[ch] + bdst, bsrc + (size_t)kt * Dc);
        cp_commit();
    }

    for (int i = 0; i < NCHUNK; i++) {
        asm volatile("cp.async.wait_group 2;\n");
        __syncthreads();

        if (i + 3 < NCHUNK) {
            int s = (i + 3) & 3;
            int kt = (i + 3) * KCH;
#pragma unroll
            for (int j = 0; j < 2; j++) cp_async16(a_base[s] + adst[j], asrc[j] + kt);
            cp_async16(b_base[s] + bdst, bsrc + (size_t)kt * Dc);
        }
        cp_commit();

        uint32_t ab = a_base[i & 3], bb = b_base[i & 3];
        uint32_t aF[2][2][4];    // [kk][mt]
        uint32_t bF[2][2][4];    // [kk][g]
#pragma unroll
        for (int kk = 0; kk < 2; kk++)
#pragma unroll
            for (int mt = 0; mt < 2; mt++) ldm4(aF[kk][mt], ab + a_off[mt][kk]);
#pragma unroll
        for (int kk = 0; kk < 2; kk++)
#pragma unroll
            for (int g = 0; g < 2; g++) ldm4t(bF[kk][g], bb + b_off[g][kk]);

#pragma unroll
        for (int kk = 0; kk < 2; kk++)
#pragma unroll
            for (int mt = 0; mt < 2; mt++)
#pragma unroll
                for (int nt = 0; nt < 4; nt++) {
                    int g = nt >> 1, sel = nt & 1;
                    mma_f16(acc[mt][nt], aF[kk][mt],
                            bF[kk][g][sel * 2], bF[kk][g][sel * 2 + 1]);
                }
    }

    // epilogue
    float (*C)[Dc] = g_a[half][b];
#pragma unroll
    for (int mt = 0; mt < 2; mt++) {
        int r_a = row0 + wm * 32 + mt * 16 + (lane >> 2);
        int r_b = r_a + 8;
#pragma unroll
        for (int nt = 0; nt < 4; nt++) {
            int col = wn * 32 + nt * 8 + (lane & 3) * 2;
            if (r_a < Nc) *(float2*)&C[r_a][col] = make_float2(acc[mt][nt][0], acc[mt][nt][1]);
            if (r_b < Nc) *(float2*)&C[r_b][col] = make_float2(acc[mt][nt][2], acc[mt][nt][3]);
        }
    }
}

// ---------------------------------------------------------------------------
// GRU update. a = [a_in | a_out | state] (192)
// ---------------------------------------------------------------------------
__global__ void k_gru(const float* __restrict__ ext_state, int use_ext, int out_idx,
                      const float* __restrict__ W_r,
                      const float* __restrict__ W_z,
                      const float* __restrict__ W_h) {
    __shared__ float a_sm[16][192];
    __shared__ float rs_sm[16][64];
    int t = threadIdx.x;
    int base = blockIdx.x * 16;

#pragma unroll
    for (int c = 0; c < 3; c++) {
        int idx = c * 256 + t;
        int lr  = idx / 48;
        int j4  = idx % 48;
        int bn  = base + lr;
        int b = bn / Nc, n = bn % Nc;
        float4 v;
        if (j4 < 16)      v = *(const float4*)&g_a[0][b][n][j4 * 4];
        else if (j4 < 32) v = *(const float4*)&g_a[1][b][n][(j4 - 16) * 4];
        else {
            const float* sp = use_ext ? (ext_state + (size_t)bn * Dc)
                                      : &g_state[0][b][n][0];
            v = *(const float4*)&sp[(j4 - 32) * 4];
        }
        *(float4*)&a_sm[lr][j4 * 4] = v;
    }
    __syncthreads();

    int f = t & 63, q = t >> 6;
    const float4* Wr4 = (const float4*)(W_r + (size_t)f * 192);
    const float4* Wz4 = (const float4*)(W_z + (size_t)f * 192);
    const float4* Wh4 = (const float4*)(W_h + (size_t)f * 192);

    float pr[4] = {0, 0, 0, 0}, pz[4] = {0, 0, 0, 0}, h1[4] = {0, 0, 0, 0};

#pragma unroll 4
    for (int j4 = 0; j4 < 32; j4++) {
        float4 wr = Wr4[j4], wz = Wz4[j4], wh = Wh4[j4];
#pragma unroll
        for (int g = 0; g < 4; g++) {
            float4 av = *(float4*)&a_sm[q * 4 + g][j4 * 4];
            pr[g] += wr.x * av.x + wr.y * av.y + wr.z * av.z + wr.w * av.w;
            pz[g] += wz.x * av.x + wz.y * av.y + wz.z * av.z + wz.w * av.w;
            h1[g] += wh.x * av.x + wh.y * av.y + wh.z * av.z + wh.w * av.w;
        }
    }
#pragma unroll 4
    for (int j4 = 32; j4 < 48; j4++) {
        float4 wr = Wr4[j4], wz = Wz4[j4];
#pragma unroll
        for (int g = 0; g < 4; g++) {
            float4 av = *(float4*)&a_sm[q * 4 + g][j4 * 4];
            pr[g] += wr.x * av.x + wr.y * av.y + wr.z * av.z + wr.w * av.w;
            pz[g] += wz.x * av.x + wz.y * av.y + wz.z * av.z + wz.w * av.w;
        }
    }

#pragma unroll
    for (int g = 0; g < 4; g++) {
        float r = 1.f / (1.f + expf(-pr[g]));
        rs_sm[q * 4 + g][f] = r * a_sm[q * 4 + g][128 + f];
    }
    __syncthreads();

#pragma unroll 4
    for (int j4 = 0; j4 < 16; j4++) {
        float4 wh = Wh4[32 + j4];
#pragma unroll
        for (int g = 0; g < 4; g++) {
            float4 rv = *(float4*)&rs_sm[q * 4 + g][j4 * 4];
            h1[g] += wh.x * rv.x + wh.y * rv.y + wh.z * rv.z + wh.w * rv.w;
        }
    }

#pragma unroll
    for (int g = 0; g < 4; g++) {
        int lr = q * 4 + g;
        int bn = base + lr;
        int b = bn / Nc, n = bn % Nc;
        float st = a_sm[lr][128 + f];
        float z  = 1.f / (1.f + expf(-pz[g]));
        float h  = tanhf(h1[g]);
        g_state[out_idx][b][n][f] = (1.f - z) * st + z * h;
    }
}

// ---------------------------------------------------------------------------
// out[b,n] = sum_f tanh( sum_{j<96} [s2|annot][j] * Wo1[f,j] ) * Wo2[f]
// ---------------------------------------------------------------------------
__global__ void k_final(const float* __restrict__ annotation,
                        const float* __restrict__ Wo1,
                        const float* __restrict__ Wo2,
                        float* __restrict__ out) {
    __shared__ float join[4][96];
    __shared__ float terms[4][64];
    int t = threadIdx.x;
    int base = blockIdx.x * 4;

    for (int idx = t; idx < 4 * 96; idx += 256) {
        int lr = idx / 96, j = idx % 96;
        int bn = base + lr;
        int b = bn / Nc, n = bn % Nc;
        join[lr][j] = (j < Dc) ? g_state[1][b][n][j]
                               : annotation[(size_t)bn * ADc + (j - Dc)];
    }
    __syncthreads();

    int f = t & 63, q = t >> 6;
    const float4* w = (const float4*)(Wo1 + (size_t)f * 96);
    float acc = 0.f;
#pragma unroll
    for (int j4 = 0; j4 < 24; j4++) {
        float4 wv = w[j4];
        float4 jv = *(float4*)&join[q][j4 * 4];
        acc += wv.x * jv.x + wv.y * jv.y + wv.z * jv.z + wv.w * jv.w;
    }
    terms[q][f] = tanhf(acc) * Wo2[f];
    __syncthreads();

    if (f == 0) {
        float s = 0.f;
#pragma unroll
        for (int i = 0; i < Dc; i++) s += terms[q][i];
        out[base + q] = s;
    }
}

// ---------------------------------------------------------------------------
extern "C" void kernel_launch(void* const* d_in, const int* in_sizes, int n_in,
                              void* d_out, int out_size) {
    const float* prop_state = (const float*)d_in[0];
    const float* annotation = (const float*)d_in[1];
    const float* A          = (const float*)d_in[2];
    const float* W_in       = (const float*)d_in[3];
    const float* W_out      = (const float*)d_in[4];
    const float* W_r        = (const float*)d_in[5];
    const float* W_z        = (const float*)d_in[6];
    const float* W_h        = (const float*)d_in[7];
    const float* Wo1        = (const float*)d_in[8];
    const float* Wo2        = (const float*)d_in[9];
    float* out = (float*)d_out;

    dim3 s_grid(125, 8);
    dim3 gemm_grid(8, 2, Bc);

    // A -> fp16 once (64M floats / 4 per thread / 256 per block)
    k_convA<<<Bc * Nc * ACOLS / 4 / 256, 256>>>(A);

    // ---- propagate step 1 (state = prop_state) ----
    k_compute_s2<<<s_grid, 256>>>(prop_state, 1, W_in, W_out);
    k_biggemm_f16<<<gemm_grid, 256>>>(0);
    k_gru<<<Bc * Nc / 16, 256>>>(prop_state, 1, 0, W_r, W_z, W_h);

    // ---- propagate step 2 (state = g_state[0]) ----
    k_compute_s2<<<s_grid, 256>>>(nullptr, 0, W_in, W_out);
    k_biggemm_f16<<<gemm_grid, 256>>>(0);
    k_gru<<<Bc * Nc / 16, 256>>>(nullptr, 0, 1, W_r, W_z, W_h);

    // ---- output head ----
    k_final<<<Bc * Nc / 4, 256>>>(annotation, Wo1, Wo2, out);
}